// round 16
// baseline (speedup 1.0000x reference)
#include <cuda_runtime.h>
#include <cuda_fp16.h>
#include <math.h>
#include <stdint.h>

// ---------------- problem constants ----------------
#define B_   16
#define L_   1024
#define DM   512      // d_model
#define ED   1024     // d_inner
#define NST  16       // d_state
#define NL   4
#define DR   32       // dt_rank
#define CH   8        // scan chunks
#define LC   128      // chunk length  (CH*LC == L_)
#define MROWS (B_*L_) // 16384

// ---------------- scratch (device globals; no allocation allowed) ----------------
__device__ __align__(16) float  g_h    [(size_t)MROWS*DM];
__device__ __align__(16) __half g_xz   [(size_t)MROWS*2*ED];
__device__ __align__(16) __half g_xc   [(size_t)MROWS*ED];
__device__ __align__(16) __half g_dbc  [(size_t)MROWS*64];
__device__ __align__(16) __half g_delta[(size_t)MROWS*ED];
__device__ __align__(16) float  g_hloc [(size_t)B_*CH*ED*NST];
__device__ __align__(16) float  g_sd   [(size_t)B_*CH*ED];
__device__ __align__(16) float  g_xT   [(size_t)MROWS*32];
__device__ __align__(16) __half g_a  [(size_t)MROWS*ED];
__device__ __align__(16) __half g_wi [(size_t)NL*2*ED*DM];
__device__ __align__(16) __half g_wo [(size_t)NL*DM*ED];
__device__ __align__(16) __half g_wx [(size_t)NL*64*ED];
__device__ __align__(16) __half g_wd [(size_t)NL*ED*DR];

__device__ __forceinline__ float sigmoidf_(float x) { return 1.f / (1.f + __expf(-x)); }

// ================= mma.sync fp16 helpers (non-arch-gated PTX) =================
__device__ __forceinline__ void ldm_x4(uint32_t (&r)[4], uint32_t a) {
    asm volatile("ldmatrix.sync.aligned.m8n8.x4.shared.b16 {%0,%1,%2,%3}, [%4];"
                 : "=r"(r[0]), "=r"(r[1]), "=r"(r[2]), "=r"(r[3]) : "r"(a));
}
__device__ __forceinline__ void mma_fp16(float (&d)[4], const uint32_t (&a)[4],
                                         uint32_t b0, uint32_t b1) {
    asm volatile(
        "mma.sync.aligned.m16n8k16.row.col.f32.f16.f16.f32 "
        "{%0,%1,%2,%3}, {%4,%5,%6,%7}, {%8,%9}, {%0,%1,%2,%3};"
        : "+f"(d[0]), "+f"(d[1]), "+f"(d[2]), "+f"(d[3])
        : "r"(a[0]), "r"(a[1]), "r"(a[2]), "r"(a[3]), "r"(b0), "r"(b1));
}
__device__ __forceinline__ void cp_async16(uint32_t sdst, const void* gsrc) {
    asm volatile("cp.async.cg.shared.global [%0], [%1], 16;" :: "r"(sdst), "l"(gsrc));
}
__device__ __forceinline__ void cp_commit() { asm volatile("cp.async.commit_group;"); }
__device__ __forceinline__ void cp_wait1()  { asm volatile("cp.async.wait_group 1;"); }
__device__ __forceinline__ void cp_wait0()  { asm volatile("cp.async.wait_group 0;"); }

__device__ __forceinline__ float softplusf_(float v) {
    return (v > 20.f) ? v : __logf(1.f + __expf(v));
}

// log-depth powers: pw[n] = r^(n+1), n=0..15
__device__ __forceinline__ void powers16(float r, float (&pw)[16]) {
    float r2 = r*r, r3 = r2*r, r4 = r2*r2;
    float r5 = r4*r, r6 = r4*r2, r7 = r4*r3, r8 = r4*r4;
    pw[0]=r;  pw[1]=r2; pw[2]=r3; pw[3]=r4;
    pw[4]=r5; pw[5]=r6; pw[6]=r7; pw[7]=r8;
    pw[8]=r8*r;  pw[9]=r8*r2;  pw[10]=r8*r3;  pw[11]=r8*r4;
    pw[12]=r8*r5; pw[13]=r8*r6; pw[14]=r8*r7; pw[15]=r8*r8;
}

// ================= fp16 tensor-core GEMM (wide tiles) =================
// MODE 0: store fp16. MODE 1: fp32 C += result. MODE 2: softplus(+bias) fp16.
#define ROWB    80
#define A_TEN   (128*ROWB)
#define B_TEN   (256*ROWB)
#define STG_SZ  (A_TEN + B_TEN)
#define MMA_SMEM (3*STG_SZ)

template<int MODE>
__global__ __launch_bounds__(512, 1)
void mma_gemm(const __half* __restrict__ A, const __half* __restrict__ B,
              void* __restrict__ C, const float* __restrict__ bias,
              int K, int lda, int ldb, int ldc) {
    extern __shared__ char smem[];
    const uint32_t sbase = (uint32_t)__cvta_generic_to_shared(smem);
    const int tid  = threadIdx.x;
    const int wid  = tid >> 5, lane = tid & 31;
    const int wm   = wid & 3;
    const int wn   = wid >> 2;
    const int bm   = blockIdx.y * 128;
    const int bn   = blockIdx.x * 256;
    const int NC   = K >> 5;

    float acc[2][8][4];
#pragma unroll
    for (int i = 0; i < 2; i++)
#pragma unroll
        for (int j = 0; j < 8; j++)
#pragma unroll
            for (int q = 0; q < 4; q++) acc[i][j][q] = 0.f;

    const int arow  = tid >> 2,          akc = tid & 3;
    const int brow0 = tid >> 2,          bkc0 = tid & 3;
    const int brow1 = (tid + 512) >> 2,  bkc1 = tid & 3;

    const __half* gA  = A + (size_t)(bm + arow)  * lda + akc  * 8;
    const __half* gB0 = B + (size_t)(bn + brow0) * ldb + bkc0 * 8;
    const __half* gB1 = B + (size_t)(bn + brow1) * ldb + bkc1 * 8;
    const uint32_t sA  = sbase + arow  * ROWB + akc  * 16;
    const uint32_t sB0 = sbase + brow0 * ROWB + bkc0 * 16;
    const uint32_t sB1 = sbase + brow1 * ROWB + bkc1 * 16;

#define LOAD_STAGE(c, s) do {                                          \
        int koff = (c) << 5;                                           \
        uint32_t st = (uint32_t)(s) * STG_SZ;                          \
        cp_async16(sA  + st,         gA  + koff);                      \
        cp_async16(sB0 + st + A_TEN, gB0 + koff);                      \
        cp_async16(sB1 + st + A_TEN, gB1 + koff);                      \
        cp_commit();                                                   \
    } while (0)

    LOAD_STAGE(0, 0);
    if (NC > 1) LOAD_STAGE(1, 1);

    const int aRow = (lane & 15);
    const int aKby = ((lane >> 4) << 4);
    const int bRow = (lane & 7) | ((lane >> 4) << 3);
    const int bKby = (((lane >> 3) & 1) << 4);

    int stg = 0;
    for (int c = 0; c < NC; c++) {
        if (c + 1 < NC) cp_wait1(); else cp_wait0();
        __syncthreads();
        int nstg = stg + 2; if (nstg >= 3) nstg -= 3;
        if (c + 2 < NC) LOAD_STAGE(c + 2, nstg);

        const uint32_t st  = sbase + (uint32_t)stg * STG_SZ;
        const uint32_t sA_ = st;
        const uint32_t sB_ = st + A_TEN;

        uint32_t af[2][2][4];
#pragma unroll
        for (int mf = 0; mf < 2; mf++) {
            uint32_t off = (uint32_t)(wm*32 + mf*16 + aRow) * ROWB + aKby;
            ldm_x4(af[0][mf], sA_ + off);
        }
#pragma unroll
        for (int k16 = 0; k16 < 2; k16++) {
            const int kb = k16 * 32;
            if (k16 == 0) {
#pragma unroll
                for (int mf = 0; mf < 2; mf++) {
                    uint32_t off = (uint32_t)(wm*32 + mf*16 + aRow) * ROWB + 32 + aKby;
                    ldm_x4(af[1][mf], sA_ + off);
                }
            }
#pragma unroll
            for (int nf2 = 0; nf2 < 4; nf2++) {
                uint32_t bf[4];
                uint32_t off = (uint32_t)(wn*64 + nf2*16 + bRow) * ROWB + kb + bKby;
                ldm_x4(bf, sB_ + off);
#pragma unroll
                for (int half = 0; half < 2; half++) {
#pragma unroll
                    for (int mf = 0; mf < 2; mf++) {
                        int nf = nf2*2 + half;
                        mma_fp16(acc[mf][nf], af[k16][mf], bf[half*2], bf[half*2+1]);
                    }
                }
            }
        }
        stg++; if (stg >= 3) stg = 0;
    }

    const int erow = lane >> 2;
    const int ecol = (lane & 3) * 2;
#pragma unroll
    for (int mf = 0; mf < 2; mf++) {
#pragma unroll
        for (int nf = 0; nf < 8; nf++) {
            int row0 = bm + wm*32 + mf*16 + erow;
            int col  = bn + wn*64 + nf*8 + ecol;
            if (MODE == 0) {
                __half* Ch = (__half*)C;
                *reinterpret_cast<__half2*>(Ch + (size_t)row0 * ldc + col) =
                    __floats2half2_rn(acc[mf][nf][0], acc[mf][nf][1]);
                *reinterpret_cast<__half2*>(Ch + (size_t)(row0 + 8) * ldc + col) =
                    __floats2half2_rn(acc[mf][nf][2], acc[mf][nf][3]);
            } else if (MODE == 1) {
                float* Cf = (float*)C;
                float* p0 = Cf + (size_t)row0 * ldc + col;
                float* p1 = Cf + (size_t)(row0 + 8) * ldc + col;
                float2 o0 = *reinterpret_cast<float2*>(p0);
                float2 o1 = *reinterpret_cast<float2*>(p1);
                o0.x += acc[mf][nf][0]; o0.y += acc[mf][nf][1];
                o1.x += acc[mf][nf][2]; o1.y += acc[mf][nf][3];
                *reinterpret_cast<float2*>(p0) = o0;
                *reinterpret_cast<float2*>(p1) = o1;
            } else {
                __half* Ch = (__half*)C;
                float b0 = bias[col], b1 = bias[col+1];
                *reinterpret_cast<__half2*>(Ch + (size_t)row0 * ldc + col) =
                    __floats2half2_rn(softplusf_(acc[mf][nf][0] + b0),
                                      softplusf_(acc[mf][nf][1] + b1));
                *reinterpret_cast<__half2*>(Ch + (size_t)(row0 + 8) * ldc + col) =
                    __floats2half2_rn(softplusf_(acc[mf][nf][2] + b0),
                                      softplusf_(acc[mf][nf][3] + b1));
            }
        }
    }
#undef LOAD_STAGE
}

// ================= fp16 tensor-core GEMM, narrow N=64 (dbc) =================
#define B64_TEN (64*ROWB)
#define STG64   (A_TEN + B64_TEN)
#define N64_SMEM (3*STG64)

__global__ __launch_bounds__(256, 1)
void tc_gemm_n64(const __half* __restrict__ A, const __half* __restrict__ B,
                 __half* __restrict__ C, int K, int lda, int ldb, int ldc) {
    extern __shared__ char smem[];
    const uint32_t sbase = (uint32_t)__cvta_generic_to_shared(smem);
    const int tid  = threadIdx.x;
    const int wid  = tid >> 5, lane = tid & 31;
    const int wm   = wid & 3;
    const int wn   = wid >> 2;
    const int bm   = blockIdx.y * 128;
    const int NC   = K >> 5;

    float acc[2][4][4];
#pragma unroll
    for (int i = 0; i < 2; i++)
#pragma unroll
        for (int j = 0; j < 4; j++)
#pragma unroll
            for (int q = 0; q < 4; q++) acc[i][j][q] = 0.f;

    const int arow0 = tid >> 2,        akc = tid & 3;
    const int arow1 = (tid + 256) >> 2;
    const int brow  = tid >> 2,        bkc = tid & 3;

    const __half* gA0 = A + (size_t)(bm + arow0) * lda + akc * 8;
    const __half* gA1 = A + (size_t)(bm + arow1) * lda + akc * 8;
    const __half* gB  = B + (size_t)brow * ldb + bkc * 8;
    const uint32_t sA0 = sbase + arow0 * ROWB + akc * 16;
    const uint32_t sA1 = sbase + arow1 * ROWB + akc * 16;
    const uint32_t sBr = sbase + brow  * ROWB + bkc * 16;

#define LOAD_STG64(c, s) do {                                          \
        int koff = (c) << 5;                                           \
        uint32_t st = (uint32_t)(s) * STG64;                           \
        cp_async16(sA0 + st,         gA0 + koff);                      \
        cp_async16(sA1 + st,         gA1 + koff);                      \
        cp_async16(sBr + st + A_TEN, gB  + koff);                      \
        cp_commit();                                                   \
    } while (0)

    LOAD_STG64(0, 0);
    if (NC > 1) LOAD_STG64(1, 1);

    const int aRow = (lane & 15);
    const int aKby = ((lane >> 4) << 4);
    const int bRow = (lane & 7) | ((lane >> 4) << 3);
    const int bKby = (((lane >> 3) & 1) << 4);

    int stg = 0;
    for (int c = 0; c < NC; c++) {
        if (c + 1 < NC) cp_wait1(); else cp_wait0();
        __syncthreads();
        int nstg = stg + 2; if (nstg >= 3) nstg -= 3;
        if (c + 2 < NC) LOAD_STG64(c + 2, nstg);

        const uint32_t st  = sbase + (uint32_t)stg * STG64;
        const uint32_t sA_ = st;
        const uint32_t sB_ = st + A_TEN;

#pragma unroll
        for (int k16 = 0; k16 < 2; k16++) {
            const int kb = k16 * 32;
            uint32_t af[2][4];
#pragma unroll
            for (int mf = 0; mf < 2; mf++) {
                uint32_t off = (uint32_t)(wm*32 + mf*16 + aRow) * ROWB + kb + aKby;
                ldm_x4(af[mf], sA_ + off);
            }
#pragma unroll
            for (int nf2 = 0; nf2 < 2; nf2++) {
                uint32_t bf[4];
                uint32_t off = (uint32_t)(wn*32 + nf2*16 + bRow) * ROWB + kb + bKby;
                ldm_x4(bf, sB_ + off);
#pragma unroll
                for (int half = 0; half < 2; half++) {
#pragma unroll
                    for (int mf = 0; mf < 2; mf++) {
                        int nf = nf2*2 + half;
                        mma_fp16(acc[mf][nf], af[mf], bf[half*2], bf[half*2+1]);
                    }
                }
            }
        }
        stg++; if (stg >= 3) stg = 0;
    }

    const int erow = lane >> 2;
    const int ecol = (lane & 3) * 2;
#pragma unroll
    for (int mf = 0; mf < 2; mf++) {
#pragma unroll
        for (int nf = 0; nf < 4; nf++) {
            int row0 = bm + wm*32 + mf*16 + erow;
            int col  = wn*32 + nf*8 + ecol;
            *reinterpret_cast<__half2*>(C + (size_t)row0 * ldc + col) =
                __floats2half2_rn(acc[mf][nf][0], acc[mf][nf][1]);
            *reinterpret_cast<__half2*>(C + (size_t)(row0 + 8) * ldc + col) =
                __floats2half2_rn(acc[mf][nf][2], acc[mf][nf][3]);
        }
    }
#undef LOAD_STG64
}

// ---------------- fp32 -> fp16 ----------------
__global__ void cvt_fp16_kernel(const float* __restrict__ x, __half* __restrict__ h, int n) {
    int i = blockIdx.x * 256 + threadIdx.x;
    if (i < n) h[i] = __float2half_rn(x[i]);
}

// ---------------- transpose x ----------------
__global__ void transpose_x_kernel(const float* __restrict__ x, float* __restrict__ xT) {
    __shared__ float t[32][33];
    int b  = blockIdx.y;
    int l0 = blockIdx.x * 32;
    int tx = threadIdx.x, ty = threadIdx.y;
    t[ty][tx] = x[((size_t)b*32 + ty)*L_ + l0 + tx];
    __syncthreads();
    xT[((size_t)b*L_ + l0 + ty)*32 + tx] = t[tx][ty];
}

// ---------------- fp32 SGEMM (embed only) ----------------
template<int BM, int BN, int BK, int TM, int TN>
__global__ __launch_bounds__((BM/TM)*(BN/TN))
void sgemm_kernel(const float* __restrict__ A, const float* __restrict__ Bw,
                  float* __restrict__ C, const float* __restrict__ bias,
                  int M, int N, int K, int lda, int ldb, int ldc) {
    constexpr int THREADS = (BM/TM)*(BN/TN);
    __shared__ float As[BK][BM];
    __shared__ float Bs[BK][BN];
    const int tid = threadIdx.x;
    const int bm  = blockIdx.y * BM;
    const int bn  = blockIdx.x * BN;
    const int tx  = tid % (BN/TN);
    const int ty  = tid / (BN/TN);

    float acc[TM][TN];
#pragma unroll
    for (int i = 0; i < TM; i++)
#pragma unroll
        for (int j = 0; j < TN; j++) acc[i][j] = 0.f;

    constexpr int AVEC = BM*BK/4/THREADS;
    constexpr int BVEC = BN*BK/4/THREADS;

    for (int k0 = 0; k0 < K; k0 += BK) {
#pragma unroll
        for (int i = 0; i < AVEC; i++) {
            int idx = tid + i*THREADS;
            int row = idx / (BK/4);
            int kc  = (idx % (BK/4)) * 4;
            float4 v = *reinterpret_cast<const float4*>(&A[(size_t)(bm+row)*lda + k0 + kc]);
            As[kc+0][row] = v.x; As[kc+1][row] = v.y; As[kc+2][row] = v.z; As[kc+3][row] = v.w;
        }
#pragma unroll
        for (int i = 0; i < BVEC; i++) {
            int idx = tid + i*THREADS;
            int row = idx / (BK/4);
            int kc  = (idx % (BK/4)) * 4;
            float4 v = *reinterpret_cast<const float4*>(&Bw[(size_t)(bn+row)*ldb + k0 + kc]);
            Bs[kc+0][row] = v.x; Bs[kc+1][row] = v.y; Bs[kc+2][row] = v.z; Bs[kc+3][row] = v.w;
        }
        __syncthreads();
#pragma unroll
        for (int kk = 0; kk < BK; kk++) {
            float a[TM], b[TN];
#pragma unroll
            for (int i = 0; i < TM; i++) a[i] = As[kk][ty*TM + i];
#pragma unroll
            for (int j = 0; j < TN; j++) b[j] = Bs[kk][tx*TN + j];
#pragma unroll
            for (int i = 0; i < TM; i++)
#pragma unroll
                for (int j = 0; j < TN; j++)
                    acc[i][j] = fmaf(a[i], b[j], acc[i][j]);
        }
        __syncthreads();
    }

#pragma unroll
    for (int i = 0; i < TM; i++) {
        int row = bm + ty*TM + i;
#pragma unroll
        for (int j = 0; j < TN; j++) {
            int col = bn + tx*TN + j;
            C[(size_t)row*ldc + col] = acc[i][j] + bias[col];
        }
    }
}

// ---------------- RMSNorm, fp16 output ----------------
__global__ void rmsnorm_kernel(const float* __restrict__ x, const float* __restrict__ w,
                               __half* __restrict__ oa) {
    int row = blockIdx.x;
    int tid = threadIdx.x;
    const float4* xr = reinterpret_cast<const float4*>(x + (size_t)row*DM);
    float4 v = xr[tid];
    float ss = v.x*v.x + v.y*v.y + v.z*v.z + v.w*v.w;
#pragma unroll
    for (int o = 16; o; o >>= 1) ss += __shfl_xor_sync(0xffffffffu, ss, o);
    __shared__ float sred[4];
    if ((tid & 31) == 0) sred[tid >> 5] = ss;
    __syncthreads();
    float tot = sred[0] + sred[1] + sred[2] + sred[3];
    float scale = rsqrtf(tot * (1.f/(float)DM) + 1e-5f);
    float4 wv = reinterpret_cast<const float4*>(w)[tid];
    float o0 = v.x*scale*wv.x, o1 = v.y*scale*wv.y, o2 = v.z*scale*wv.z, o3 = v.w*scale*wv.w;
    size_t off = (size_t)row*DM + tid*4;
    __half2* oa2 = reinterpret_cast<__half2*>(oa + off);
    oa2[0] = __floats2half2_rn(o0, o1);
    oa2[1] = __floats2half2_rn(o2, o3);
}

// ---------------- depthwise causal conv(4) + bias + silu ----------------
__device__ __forceinline__ float4 ld_half4(const __half* p) {
    uint2 u = *reinterpret_cast<const uint2*>(p);
    float2 f01 = __half22float2(*reinterpret_cast<__half2*>(&u.x));
    float2 f23 = __half22float2(*reinterpret_cast<__half2*>(&u.y));
    return make_float4(f01.x, f01.y, f23.x, f23.y);
}
__global__ void conv_silu_kernel(const __half* __restrict__ xz, const float* __restrict__ cw,
                                 const float* __restrict__ cb, __half* __restrict__ out) {
    size_t idx = (size_t)blockIdx.x * 256 + threadIdx.x;
    int e4 = (idx & (ED/4 - 1)) * 4;
    size_t rg = idx >> 8;
    int l0 = (int)(rg & (L_/4 - 1)) * 4;
    size_t row0 = (rg >> 8) * (size_t)L_ + l0;

    float4 b4 = *reinterpret_cast<const float4*>(&cb[e4]);
    float4 w0 = *reinterpret_cast<const float4*>(&cw[(size_t)(e4+0)*4]);
    float4 w1 = *reinterpret_cast<const float4*>(&cw[(size_t)(e4+1)*4]);
    float4 w2 = *reinterpret_cast<const float4*>(&cw[(size_t)(e4+2)*4]);
    float4 w3 = *reinterpret_cast<const float4*>(&cw[(size_t)(e4+3)*4]);

    float4 v[7];
#pragma unroll
    for (int i = 0; i < 7; i++) {
        int l = l0 - 3 + i;
        if (l >= 0) v[i] = ld_half4(xz + (row0 + (i - 3)) * (size_t)(2*ED) + e4);
        else        v[i] = make_float4(0.f, 0.f, 0.f, 0.f);
    }

#pragma unroll
    for (int j = 0; j < 4; j++) {
        float4 acc = b4;
        acc.x = fmaf(w0.x, v[j].x,   acc.x); acc.y = fmaf(w1.x, v[j].y,   acc.y);
        acc.z = fmaf(w2.x, v[j].z,   acc.z); acc.w = fmaf(w3.x, v[j].w,   acc.w);
        acc.x = fmaf(w0.y, v[j+1].x, acc.x); acc.y = fmaf(w1.y, v[j+1].y, acc.y);
        acc.z = fmaf(w2.y, v[j+1].z, acc.z); acc.w = fmaf(w3.y, v[j+1].w, acc.w);
        acc.x = fmaf(w0.z, v[j+2].x, acc.x); acc.y = fmaf(w1.z, v[j+2].y, acc.y);
        acc.z = fmaf(w2.z, v[j+2].z, acc.z); acc.w = fmaf(w3.z, v[j+2].w, acc.w);
        acc.x = fmaf(w0.w, v[j+3].x, acc.x); acc.y = fmaf(w1.w, v[j+3].y, acc.y);
        acc.z = fmaf(w2.w, v[j+3].z, acc.z); acc.w = fmaf(w3.w, v[j+3].w, acc.w);
        float4 o;
        o.x = acc.x * sigmoidf_(acc.x); o.y = acc.y * sigmoidf_(acc.y);
        o.z = acc.z * sigmoidf_(acc.z); o.w = acc.w * sigmoidf_(acc.w);
        uint2 st;
        *reinterpret_cast<__half2*>(&st.x) = __floats2half2_rn(o.x, o.y);
        *reinterpret_cast<__half2*>(&st.y) = __floats2half2_rn(o.z, o.w);
        *reinterpret_cast<uint2*>(&out[(row0 + j) * (size_t)ED + e4]) = st;
    }
}

// ---------------- scan pass A: local scan; writes hloc + scalar sd ----------------
__global__ __launch_bounds__(256)
void scan_passA(const __half* __restrict__ delta, const __half* __restrict__ u,
                const __half* __restrict__ dbc, const float* __restrict__ A_log,
                float* __restrict__ hloc, float* __restrict__ sdv) {
    __shared__ float sB[LC][NST];
    int e = blockIdx.x * 256 + threadIdx.x;
    int c = blockIdx.y, b = blockIdx.z;
    for (int i = threadIdx.x; i < LC*NST; i += 256) {
        int row = i >> 4, col = i & 15;
        sB[row][col] = __half2float(dbc[(size_t)(b*L_ + c*LC + row)*64 + 32 + col]);
    }
    __syncthreads();

    float A[NST];
    bool fast = true;
#pragma unroll
    for (int n = 0; n < NST; n++) {
        float a = -__expf(A_log[(size_t)e*NST + n]);
        A[n] = a;
        fast = fast && (fabsf(a + (float)(n+1)) < 1e-4f * (float)(n+1));
    }

    float h[NST];
#pragma unroll
    for (int n = 0; n < NST; n++) h[n] = 0.f;
    float sd = 0.f;
    const __half* dp = delta + (size_t)(b*L_ + c*LC)*ED + e;
    const __half* up = u     + (size_t)(b*L_ + c*LC)*ED + e;

    if (fast) {
        for (int l = 0; l < LC; l++) {
            float dl = __half2float(dp[(size_t)l*ED]);
            float ul = __half2float(up[(size_t)l*ED]);
            float r  = __expf(-dl);
            float du = dl * ul;
            sd += dl;
            float pw[16];
            powers16(r, pw);
#pragma unroll
            for (int n = 0; n < NST; n++)
                h[n] = fmaf(pw[n], h[n], du * sB[l][n]);
        }
    } else {
        for (int l = 0; l < LC; l++) {
            float dl = __half2float(dp[(size_t)l*ED]);
            float ul = __half2float(up[(size_t)l*ED]);
            float du = dl * ul;
            sd += dl;
#pragma unroll
            for (int n = 0; n < NST; n++) {
                float dA = __expf(dl * A[n]);
                h[n] = fmaf(dA, h[n], du * sB[l][n]);
            }
        }
    }
    size_t oc = (size_t)(b*CH + c)*ED + e;
    size_t o  = oc*NST;
#pragma unroll
    for (int n4 = 0; n4 < NST; n4 += 4)
        *reinterpret_cast<float4*>(&hloc[o + n4]) =
            make_float4(h[n4], h[n4+1], h[n4+2], h[n4+3]);
    sdv[oc] = sd;
}

// ---------------- scan pass B: inline prefix fold + re-scan + gate ----------------
__global__ __launch_bounds__(256)
void scan_passB(const __half* __restrict__ delta, const __half* __restrict__ u,
                const __half* __restrict__ dbc, const __half* __restrict__ xz,
                const float* __restrict__ A_log, const float* __restrict__ Dv,
                const float* __restrict__ hloc, const float* __restrict__ sdv,
                __half* __restrict__ ya) {
    __shared__ float sB[LC][NST];
    __shared__ float sC[LC][NST];
    int e = blockIdx.x * 256 + threadIdx.x;
    int c = blockIdx.y, b = blockIdx.z;
    for (int i = threadIdx.x; i < LC*32; i += 256) {
        int row = i >> 5, col = i & 31;
        float v = __half2float(dbc[(size_t)(b*L_ + c*LC + row)*64 + 32 + col]);
        if (col < 16) sB[row][col] = v; else sC[row][col-16] = v;
    }
    __syncthreads();

    float A[NST];
    bool fast = true;
#pragma unroll
    for (int n = 0; n < NST; n++) {
        float a = -__expf(A_log[(size_t)e*NST + n]);
        A[n] = a;
        fast = fast && (fabsf(a + (float)(n+1)) < 1e-4f * (float)(n+1));
    }

    // inline prefix fold: h = state entering chunk c
    float h[NST];
#pragma unroll
    for (int n = 0; n < NST; n++) h[n] = 0.f;
    for (int cc = 0; cc < c; cc++) {
        size_t oc = (size_t)(b*CH + cc)*ED + e;
        size_t o  = oc*NST;
        float hl[NST];
#pragma unroll
        for (int n4 = 0; n4 < NST; n4 += 4) {
            float4 v = *reinterpret_cast<const float4*>(&hloc[o + n4]);
            hl[n4+0] = v.x; hl[n4+1] = v.y; hl[n4+2] = v.z; hl[n4+3] = v.w;
        }
        float sdc = sdv[oc];
        if (fast) {
            float r = __expf(-sdc);
            float pw[16];
            powers16(r, pw);
#pragma unroll
            for (int n = 0; n < NST; n++) h[n] = fmaf(pw[n], h[n], hl[n]);
        } else {
#pragma unroll
            for (int n = 0; n < NST; n++)
                h[n] = fmaf(__expf(A[n]*sdc), h[n], hl[n]);
        }
    }

    float Dp = Dv[e];
    const __half* dp = delta + (size_t)(b*L_ + c*LC)*ED + e;
    const __half* up = u     + (size_t)(b*L_ + c*LC)*ED + e;
    const __half* zp = xz    + (size_t)(b*L_ + c*LC)*(2*ED) + ED + e;
    size_t yo = (size_t)(b*L_ + c*LC)*ED + e;

    if (fast) {
        for (int l = 0; l < LC; l++) {
            float dl = __half2float(dp[(size_t)l*ED]);
            float ul = __half2float(up[(size_t)l*ED]);
            float r  = __expf(-dl);
            float du = dl * ul;
            float y  = 0.f;
            float pw[16];
            powers16(r, pw);
#pragma unroll
            for (int n = 0; n < NST; n++) {
                h[n] = fmaf(pw[n], h[n], du * sB[l][n]);
                y = fmaf(h[n], sC[l][n], y);
            }
            float zl = __half2float(zp[(size_t)l*(2*ED)]);
            float yt = fmaf(Dp, ul, y) * zl * sigmoidf_(zl);
            ya[yo + (size_t)l*ED] = __float2half_rn(yt);
        }
    } else {
        for (int l = 0; l < LC; l++) {
            float dl = __half2float(dp[(size_t)l*ED]);
            float ul = __half2float(up[(size_t)l*ED]);
            float du = dl * ul;
            float y  = 0.f;
#pragma unroll
            for (int n = 0; n < NST; n++) {
                float dA = __expf(dl * A[n]);
                h[n] = fmaf(dA, h[n], du * sB[l][n]);
                y = fmaf(h[n], sC[l][n], y);
            }
            float zl = __half2float(zp[(size_t)l*(2*ED)]);
            float yt = fmaf(Dp, ul, y) * zl * sigmoidf_(zl);
            ya[yo + (size_t)l*ED] = __float2half_rn(yt);
        }
    }
}

// ---------------- head ----------------
__global__ void head_kernel(const float* __restrict__ h, const float* __restrict__ hw,
                            const float* __restrict__ hb, float* __restrict__ out) {
    int w    = blockIdx.x * 8 + (threadIdx.x >> 5);
    int lane = threadIdx.x & 31;
    int n = w % 3072;
    int b = w / 3072;
    const float4* hr4 = reinterpret_cast<const float4*>(h + ((size_t)b*L_ + (L_-1))*DM);
    const float4* wr4 = reinterpret_cast<const float4*>(hw + (size_t)n*DM);
    float s = 0.f;
#pragma unroll
    for (int i = 0; i < 4; i++) {
        int k4 = lane + i*32;
        float4 a = hr4[k4];
        float4 ww = wr4[k4];
        s += a.x*ww.x + a.y*ww.y + a.z*ww.z + a.w*ww.w;
    }
#pragma unroll
    for (int o = 16; o; o >>= 1) s += __shfl_xor_sync(0xffffffffu, s, o);
    if (lane == 0) {
        int c = n & 31, t = n >> 5;
        out[(size_t)b*3072 + (size_t)c*96 + t] = s + hb[n];
    }
}

// ---------------- launch ----------------
extern "C" void kernel_launch(void* const* d_in, const int* in_sizes, int n_in,
                              void* d_out, int out_size) {
    const float* x        = (const float*)d_in[0];
    const float* embed_w  = (const float*)d_in[1];
    const float* embed_b  = (const float*)d_in[2];
    const float* norm_w   = (const float*)d_in[3];
    const float* in_w     = (const float*)d_in[4];
    const float* conv_w   = (const float*)d_in[5];
    const float* conv_b   = (const float*)d_in[6];
    const float* xp_w     = (const float*)d_in[7];
    const float* dt_w     = (const float*)d_in[8];
    const float* dt_b     = (const float*)d_in[9];
    const float* A_log    = (const float*)d_in[10];
    const float* Dv       = (const float*)d_in[11];
    const float* out_w    = (const float*)d_in[12];
    const float* head_w   = (const float*)d_in[13];
    const float* head_b   = (const float*)d_in[14];
    float* out = (float*)d_out;

    float *h, *hloc, *sd, *xT;
    __half *xz, *xc, *dbc, *delta, *a, *wi, *wo, *wx, *wd;
    cudaGetSymbolAddress((void**)&h,     g_h);
    cudaGetSymbolAddress((void**)&xz,    g_xz);
    cudaGetSymbolAddress((void**)&xc,    g_xc);
    cudaGetSymbolAddress((void**)&dbc,   g_dbc);
    cudaGetSymbolAddress((void**)&delta, g_delta);
    cudaGetSymbolAddress((void**)&hloc,  g_hloc);
    cudaGetSymbolAddress((void**)&sd,    g_sd);
    cudaGetSymbolAddress((void**)&xT,    g_xT);
    cudaGetSymbolAddress((void**)&a,     g_a);
    cudaGetSymbolAddress((void**)&wi,    g_wi);
    cudaGetSymbolAddress((void**)&wo,    g_wo);
    cudaGetSymbolAddress((void**)&wx,    g_wx);
    cudaGetSymbolAddress((void**)&wd,    g_wd);

    cudaFuncSetAttribute(mma_gemm<0>, cudaFuncAttributeMaxDynamicSharedMemorySize, MMA_SMEM);
    cudaFuncSetAttribute(mma_gemm<1>, cudaFuncAttributeMaxDynamicSharedMemorySize, MMA_SMEM);
    cudaFuncSetAttribute(mma_gemm<2>, cudaFuncAttributeMaxDynamicSharedMemorySize, MMA_SMEM);
    cudaFuncSetAttribute(tc_gemm_n64, cudaFuncAttributeMaxDynamicSharedMemorySize, N64_SMEM);

    transpose_x_kernel<<<dim3(L_/32, B_), dim3(32, 32)>>>(x, xT);
    cvt_fp16_kernel<<<(NL*2*ED*DM + 255)/256, 256>>>(in_w,  wi, NL*2*ED*DM);
    cvt_fp16_kernel<<<(NL*DM*ED   + 255)/256, 256>>>(out_w, wo, NL*DM*ED);
    cvt_fp16_kernel<<<(NL*64*ED   + 255)/256, 256>>>(xp_w,  wx, NL*64*ED);
    cvt_fp16_kernel<<<(NL*ED*DR   + 255)/256, 256>>>(dt_w,  wd, NL*ED*DR);
    sgemm_kernel<128,128,16,8,8><<<dim3(DM/128, MROWS/128), 256>>>(
        xT, embed_w, h, embed_b, MROWS, DM, 32, 32, 32, DM);

    for (int i = 0; i < NL; i++) {
        rmsnorm_kernel<<<MROWS, 128>>>(h, norm_w + (size_t)i*DM, a);

        // xz = rms @ in_proj^T
        mma_gemm<0><<<dim3(2*ED/256, MROWS/128), 512, MMA_SMEM>>>(
            a, wi + (size_t)i*2*ED*DM, xz, nullptr, DM, DM, DM, 2*ED);

        // depthwise causal conv + silu
        conv_silu_kernel<<<(MROWS/4)*(ED/4)/256, 256>>>(
            xz, conv_w + (size_t)i*ED*4, conv_b + (size_t)i*ED, xc);

        // dbc = xc @ x_proj^T
        tc_gemm_n64<<<dim3(1, MROWS/128), 256, N64_SMEM>>>(
            xc, wx + (size_t)i*64*ED, dbc, ED, ED, ED, 64);

        // delta = softplus(dbc[:, :32] @ dt_w^T + dt_b)
        mma_gemm<2><<<dim3(ED/256, MROWS/128), 512, MMA_SMEM>>>(
            dbc, wd + (size_t)i*ED*DR, delta, dt_b + (size_t)i*ED, DR, 64, DR, ED);

        // chunked selective scan (combine folded into pass B)
        scan_passA<<<dim3(ED/256, CH, B_), 256>>>(
            delta, xc, dbc, A_log + (size_t)i*ED*NST, hloc, sd);
        scan_passB<<<dim3(ED/256, CH, B_), 256>>>(
            delta, xc, dbc, xz, A_log + (size_t)i*ED*NST, Dv + (size_t)i*ED,
            hloc, sd, a);

        // h += y @ out_proj^T
        mma_gemm<1><<<dim3(DM/256, MROWS/128), 512, MMA_SMEM>>>(
            a, wo + (size_t)i*DM*ED, h, nullptr, ED, ED, ED, DM);
    }

    head_kernel<<<(B_*3072)/8, 256>>>(h, head_w, head_b, out);
}

// round 17
// speedup vs baseline: 1.1537x; 1.1537x over previous
#include <cuda_runtime.h>
#include <cuda_fp16.h>
#include <math.h>
#include <stdint.h>

// ---------------- problem constants ----------------
#define B_   16
#define L_   1024
#define DM   512      // d_model
#define ED   1024     // d_inner
#define NST  16       // d_state
#define NL   4
#define DR   32       // dt_rank
#define CH   8        // scan chunks
#define LC   128      // chunk length  (CH*LC == L_)
#define MROWS (B_*L_) // 16384

// ---------------- scratch (device globals; no allocation allowed) ----------------
__device__ __align__(16) __half g_h    [(size_t)MROWS*DM];   // residual stream (fp16 now)
__device__ __align__(16) __half g_xz   [(size_t)MROWS*2*ED];
__device__ __align__(16) __half g_xc   [(size_t)MROWS*ED];
__device__ __align__(16) __half g_dbc  [(size_t)MROWS*64];
__device__ __align__(16) __half g_delta[(size_t)MROWS*ED];
__device__ __align__(16) float  g_hloc [(size_t)B_*CH*ED*NST];
__device__ __align__(16) float  g_P    [(size_t)B_*CH*ED*NST];
__device__ __align__(16) float  g_Hin  [(size_t)B_*CH*ED*NST];
__device__ __align__(16) float  g_xT   [(size_t)MROWS*32];
__device__ __align__(16) __half g_a  [(size_t)MROWS*ED];
__device__ __align__(16) __half g_wi [(size_t)NL*2*ED*DM];
__device__ __align__(16) __half g_wo [(size_t)NL*DM*ED];
__device__ __align__(16) __half g_wx [(size_t)NL*64*ED];
__device__ __align__(16) __half g_wd [(size_t)NL*ED*DR];

__device__ __forceinline__ float sigmoidf_(float x) { return 1.f / (1.f + __expf(-x)); }

__device__ __forceinline__ float4 ld_half4(const __half* p) {
    uint2 u = *reinterpret_cast<const uint2*>(p);
    float2 f01 = __half22float2(*reinterpret_cast<__half2*>(&u.x));
    float2 f23 = __half22float2(*reinterpret_cast<__half2*>(&u.y));
    return make_float4(f01.x, f01.y, f23.x, f23.y);
}

// ================= mma.sync fp16 helpers (non-arch-gated PTX) =================
__device__ __forceinline__ void ldm_x4(uint32_t (&r)[4], uint32_t a) {
    asm volatile("ldmatrix.sync.aligned.m8n8.x4.shared.b16 {%0,%1,%2,%3}, [%4];"
                 : "=r"(r[0]), "=r"(r[1]), "=r"(r[2]), "=r"(r[3]) : "r"(a));
}
__device__ __forceinline__ void mma_fp16(float (&d)[4], const uint32_t (&a)[4],
                                         uint32_t b0, uint32_t b1) {
    asm volatile(
        "mma.sync.aligned.m16n8k16.row.col.f32.f16.f16.f32 "
        "{%0,%1,%2,%3}, {%4,%5,%6,%7}, {%8,%9}, {%0,%1,%2,%3};"
        : "+f"(d[0]), "+f"(d[1]), "+f"(d[2]), "+f"(d[3])
        : "r"(a[0]), "r"(a[1]), "r"(a[2]), "r"(a[3]), "r"(b0), "r"(b1));
}
__device__ __forceinline__ void cp_async16(uint32_t sdst, const void* gsrc) {
    asm volatile("cp.async.cg.shared.global [%0], [%1], 16;" :: "r"(sdst), "l"(gsrc));
}
__device__ __forceinline__ void cp_commit() { asm volatile("cp.async.commit_group;"); }
__device__ __forceinline__ void cp_wait1()  { asm volatile("cp.async.wait_group 1;"); }
__device__ __forceinline__ void cp_wait0()  { asm volatile("cp.async.wait_group 0;"); }

__device__ __forceinline__ float softplusf_(float v) {
    return (v > 20.f) ? v : __logf(1.f + __expf(v));
}

// log-depth powers: pw[n] = r^(n+1), n=0..15
__device__ __forceinline__ void powers16(float r, float (&pw)[16]) {
    float r2 = r*r, r3 = r2*r, r4 = r2*r2;
    float r5 = r4*r, r6 = r4*r2, r7 = r4*r3, r8 = r4*r4;
    pw[0]=r;  pw[1]=r2; pw[2]=r3; pw[3]=r4;
    pw[4]=r5; pw[5]=r6; pw[6]=r7; pw[7]=r8;
    pw[8]=r8*r;  pw[9]=r8*r2;  pw[10]=r8*r3;  pw[11]=r8*r4;
    pw[12]=r8*r5; pw[13]=r8*r6; pw[14]=r8*r7; pw[15]=r8*r8;
}

// ================= fp16 tensor-core GEMM (wide tiles) =================
// MODE 0: store fp16. MODE 1: fp16 C += result (fp32 accum). MODE 2: softplus(+bias) fp16.
#define ROWB    80
#define A_TEN   (128*ROWB)
#define B_TEN   (256*ROWB)
#define STG_SZ  (A_TEN + B_TEN)
#define MMA_SMEM (3*STG_SZ)

template<int MODE>
__global__ __launch_bounds__(512, 1)
void mma_gemm(const __half* __restrict__ A, const __half* __restrict__ B,
              void* __restrict__ C, const float* __restrict__ bias,
              int K, int lda, int ldb, int ldc) {
    extern __shared__ char smem[];
    const uint32_t sbase = (uint32_t)__cvta_generic_to_shared(smem);
    const int tid  = threadIdx.x;
    const int wid  = tid >> 5, lane = tid & 31;
    const int wm   = wid & 3;
    const int wn   = wid >> 2;
    const int bm   = blockIdx.y * 128;
    const int bn   = blockIdx.x * 256;
    const int NC   = K >> 5;

    float acc[2][8][4];
#pragma unroll
    for (int i = 0; i < 2; i++)
#pragma unroll
        for (int j = 0; j < 8; j++)
#pragma unroll
            for (int q = 0; q < 4; q++) acc[i][j][q] = 0.f;

    const int arow  = tid >> 2,          akc = tid & 3;
    const int brow0 = tid >> 2,          bkc0 = tid & 3;
    const int brow1 = (tid + 512) >> 2,  bkc1 = tid & 3;

    const __half* gA  = A + (size_t)(bm + arow)  * lda + akc  * 8;
    const __half* gB0 = B + (size_t)(bn + brow0) * ldb + bkc0 * 8;
    const __half* gB1 = B + (size_t)(bn + brow1) * ldb + bkc1 * 8;
    const uint32_t sA  = sbase + arow  * ROWB + akc  * 16;
    const uint32_t sB0 = sbase + brow0 * ROWB + bkc0 * 16;
    const uint32_t sB1 = sbase + brow1 * ROWB + bkc1 * 16;

#define LOAD_STAGE(c, s) do {                                          \
        int koff = (c) << 5;                                           \
        uint32_t st = (uint32_t)(s) * STG_SZ;                          \
        cp_async16(sA  + st,         gA  + koff);                      \
        cp_async16(sB0 + st + A_TEN, gB0 + koff);                      \
        cp_async16(sB1 + st + A_TEN, gB1 + koff);                      \
        cp_commit();                                                   \
    } while (0)

    LOAD_STAGE(0, 0);
    if (NC > 1) LOAD_STAGE(1, 1);

    const int aRow = (lane & 15);
    const int aKby = ((lane >> 4) << 4);
    const int bRow = (lane & 7) | ((lane >> 4) << 3);
    const int bKby = (((lane >> 3) & 1) << 4);

    int stg = 0;
    for (int c = 0; c < NC; c++) {
        if (c + 1 < NC) cp_wait1(); else cp_wait0();
        __syncthreads();
        int nstg = stg + 2; if (nstg >= 3) nstg -= 3;
        if (c + 2 < NC) LOAD_STAGE(c + 2, nstg);

        const uint32_t st  = sbase + (uint32_t)stg * STG_SZ;
        const uint32_t sA_ = st;
        const uint32_t sB_ = st + A_TEN;

        uint32_t af[2][2][4];
#pragma unroll
        for (int mf = 0; mf < 2; mf++) {
            uint32_t off = (uint32_t)(wm*32 + mf*16 + aRow) * ROWB + aKby;
            ldm_x4(af[0][mf], sA_ + off);
        }
#pragma unroll
        for (int k16 = 0; k16 < 2; k16++) {
            const int kb = k16 * 32;
            if (k16 == 0) {
#pragma unroll
                for (int mf = 0; mf < 2; mf++) {
                    uint32_t off = (uint32_t)(wm*32 + mf*16 + aRow) * ROWB + 32 + aKby;
                    ldm_x4(af[1][mf], sA_ + off);
                }
            }
#pragma unroll
            for (int nf2 = 0; nf2 < 4; nf2++) {
                uint32_t bf[4];
                uint32_t off = (uint32_t)(wn*64 + nf2*16 + bRow) * ROWB + kb + bKby;
                ldm_x4(bf, sB_ + off);
#pragma unroll
                for (int half = 0; half < 2; half++) {
#pragma unroll
                    for (int mf = 0; mf < 2; mf++) {
                        int nf = nf2*2 + half;
                        mma_fp16(acc[mf][nf], af[k16][mf], bf[half*2], bf[half*2+1]);
                    }
                }
            }
        }
        stg++; if (stg >= 3) stg = 0;
    }

    const int erow = lane >> 2;
    const int ecol = (lane & 3) * 2;
#pragma unroll
    for (int mf = 0; mf < 2; mf++) {
#pragma unroll
        for (int nf = 0; nf < 8; nf++) {
            int row0 = bm + wm*32 + mf*16 + erow;
            int col  = bn + wn*64 + nf*8 + ecol;
            __half* Ch = (__half*)C;
            __half2* p0 = reinterpret_cast<__half2*>(Ch + (size_t)row0 * ldc + col);
            __half2* p1 = reinterpret_cast<__half2*>(Ch + (size_t)(row0 + 8) * ldc + col);
            if (MODE == 0) {
                *p0 = __floats2half2_rn(acc[mf][nf][0], acc[mf][nf][1]);
                *p1 = __floats2half2_rn(acc[mf][nf][2], acc[mf][nf][3]);
            } else if (MODE == 1) {
                float2 o0 = __half22float2(*p0);
                float2 o1 = __half22float2(*p1);
                *p0 = __floats2half2_rn(o0.x + acc[mf][nf][0], o0.y + acc[mf][nf][1]);
                *p1 = __floats2half2_rn(o1.x + acc[mf][nf][2], o1.y + acc[mf][nf][3]);
            } else {
                float b0 = bias[col], b1 = bias[col+1];
                *p0 = __floats2half2_rn(softplusf_(acc[mf][nf][0] + b0),
                                        softplusf_(acc[mf][nf][1] + b1));
                *p1 = __floats2half2_rn(softplusf_(acc[mf][nf][2] + b0),
                                        softplusf_(acc[mf][nf][3] + b1));
            }
        }
    }
#undef LOAD_STAGE
}

// ================= fp16 tensor-core GEMM, narrow N=64 (dbc) =================
#define B64_TEN (64*ROWB)
#define STG64   (A_TEN + B64_TEN)
#define N64_SMEM (3*STG64)

__global__ __launch_bounds__(256, 1)
void tc_gemm_n64(const __half* __restrict__ A, const __half* __restrict__ B,
                 __half* __restrict__ C, int K, int lda, int ldb, int ldc) {
    extern __shared__ char smem[];
    const uint32_t sbase = (uint32_t)__cvta_generic_to_shared(smem);
    const int tid  = threadIdx.x;
    const int wid  = tid >> 5, lane = tid & 31;
    const int wm   = wid & 3;
    const int wn   = wid >> 2;
    const int bm   = blockIdx.y * 128;
    const int NC   = K >> 5;

    float acc[2][4][4];
#pragma unroll
    for (int i = 0; i < 2; i++)
#pragma unroll
        for (int j = 0; j < 4; j++)
#pragma unroll
            for (int q = 0; q < 4; q++) acc[i][j][q] = 0.f;

    const int arow0 = tid >> 2,        akc = tid & 3;
    const int arow1 = (tid + 256) >> 2;
    const int brow  = tid >> 2,        bkc = tid & 3;

    const __half* gA0 = A + (size_t)(bm + arow0) * lda + akc * 8;
    const __half* gA1 = A + (size_t)(bm + arow1) * lda + akc * 8;
    const __half* gB  = B + (size_t)brow * ldb + bkc * 8;
    const uint32_t sA0 = sbase + arow0 * ROWB + akc * 16;
    const uint32_t sA1 = sbase + arow1 * ROWB + akc * 16;
    const uint32_t sBr = sbase + brow  * ROWB + bkc * 16;

#define LOAD_STG64(c, s) do {                                          \
        int koff = (c) << 5;                                           \
        uint32_t st = (uint32_t)(s) * STG64;                           \
        cp_async16(sA0 + st,         gA0 + koff);                      \
        cp_async16(sA1 + st,         gA1 + koff);                      \
        cp_async16(sBr + st + A_TEN, gB  + koff);                      \
        cp_commit();                                                   \
    } while (0)

    LOAD_STG64(0, 0);
    if (NC > 1) LOAD_STG64(1, 1);

    const int aRow = (lane & 15);
    const int aKby = ((lane >> 4) << 4);
    const int bRow = (lane & 7) | ((lane >> 4) << 3);
    const int bKby = (((lane >> 3) & 1) << 4);

    int stg = 0;
    for (int c = 0; c < NC; c++) {
        if (c + 1 < NC) cp_wait1(); else cp_wait0();
        __syncthreads();
        int nstg = stg + 2; if (nstg >= 3) nstg -= 3;
        if (c + 2 < NC) LOAD_STG64(c + 2, nstg);

        const uint32_t st  = sbase + (uint32_t)stg * STG64;
        const uint32_t sA_ = st;
        const uint32_t sB_ = st + A_TEN;

#pragma unroll
        for (int k16 = 0; k16 < 2; k16++) {
            const int kb = k16 * 32;
            uint32_t af[2][4];
#pragma unroll
            for (int mf = 0; mf < 2; mf++) {
                uint32_t off = (uint32_t)(wm*32 + mf*16 + aRow) * ROWB + kb + aKby;
                ldm_x4(af[mf], sA_ + off);
            }
#pragma unroll
            for (int nf2 = 0; nf2 < 2; nf2++) {
                uint32_t bf[4];
                uint32_t off = (uint32_t)(wn*32 + nf2*16 + bRow) * ROWB + kb + bKby;
                ldm_x4(bf, sB_ + off);
#pragma unroll
                for (int half = 0; half < 2; half++) {
#pragma unroll
                    for (int mf = 0; mf < 2; mf++) {
                        int nf = nf2*2 + half;
                        mma_fp16(acc[mf][nf], af[mf], bf[half*2], bf[half*2+1]);
                    }
                }
            }
        }
        stg++; if (stg >= 3) stg = 0;
    }

    const int erow = lane >> 2;
    const int ecol = (lane & 3) * 2;
#pragma unroll
    for (int mf = 0; mf < 2; mf++) {
#pragma unroll
        for (int nf = 0; nf < 4; nf++) {
            int row0 = bm + wm*32 + mf*16 + erow;
            int col  = wn*32 + nf*8 + ecol;
            *reinterpret_cast<__half2*>(C + (size_t)row0 * ldc + col) =
                __floats2half2_rn(acc[mf][nf][0], acc[mf][nf][1]);
            *reinterpret_cast<__half2*>(C + (size_t)(row0 + 8) * ldc + col) =
                __floats2half2_rn(acc[mf][nf][2], acc[mf][nf][3]);
        }
    }
#undef LOAD_STG64
}

// ---------------- fp32 -> fp16 ----------------
__global__ void cvt_fp16_kernel(const float* __restrict__ x, __half* __restrict__ h, int n) {
    int i = blockIdx.x * 256 + threadIdx.x;
    if (i < n) h[i] = __float2half_rn(x[i]);
}

// ---------------- transpose x ----------------
__global__ void transpose_x_kernel(const float* __restrict__ x, float* __restrict__ xT) {
    __shared__ float t[32][33];
    int b  = blockIdx.y;
    int l0 = blockIdx.x * 32;
    int tx = threadIdx.x, ty = threadIdx.y;
    t[ty][tx] = x[((size_t)b*32 + ty)*L_ + l0 + tx];
    __syncthreads();
    xT[((size_t)b*L_ + l0 + ty)*32 + tx] = t[tx][ty];
}

// ---------------- fp32 SGEMM (embed only), fp16 output ----------------
template<int BM, int BN, int BK, int TM, int TN>
__global__ __launch_bounds__((BM/TM)*(BN/TN))
void sgemm_kernel(const float* __restrict__ A, const float* __restrict__ Bw,
                  __half* __restrict__ C, const float* __restrict__ bias,
                  int M, int N, int K, int lda, int ldb, int ldc) {
    constexpr int THREADS = (BM/TM)*(BN/TN);
    __shared__ float As[BK][BM];
    __shared__ float Bs[BK][BN];
    const int tid = threadIdx.x;
    const int bm  = blockIdx.y * BM;
    const int bn  = blockIdx.x * BN;
    const int tx  = tid % (BN/TN);
    const int ty  = tid / (BN/TN);

    float acc[TM][TN];
#pragma unroll
    for (int i = 0; i < TM; i++)
#pragma unroll
        for (int j = 0; j < TN; j++) acc[i][j] = 0.f;

    constexpr int AVEC = BM*BK/4/THREADS;
    constexpr int BVEC = BN*BK/4/THREADS;

    for (int k0 = 0; k0 < K; k0 += BK) {
#pragma unroll
        for (int i = 0; i < AVEC; i++) {
            int idx = tid + i*THREADS;
            int row = idx / (BK/4);
            int kc  = (idx % (BK/4)) * 4;
            float4 v = *reinterpret_cast<const float4*>(&A[(size_t)(bm+row)*lda + k0 + kc]);
            As[kc+0][row] = v.x; As[kc+1][row] = v.y; As[kc+2][row] = v.z; As[kc+3][row] = v.w;
        }
#pragma unroll
        for (int i = 0; i < BVEC; i++) {
            int idx = tid + i*THREADS;
            int row = idx / (BK/4);
            int kc  = (idx % (BK/4)) * 4;
            float4 v = *reinterpret_cast<const float4*>(&Bw[(size_t)(bn+row)*ldb + k0 + kc]);
            Bs[kc+0][row] = v.x; Bs[kc+1][row] = v.y; Bs[kc+2][row] = v.z; Bs[kc+3][row] = v.w;
        }
        __syncthreads();
#pragma unroll
        for (int kk = 0; kk < BK; kk++) {
            float a[TM], b[TN];
#pragma unroll
            for (int i = 0; i < TM; i++) a[i] = As[kk][ty*TM + i];
#pragma unroll
            for (int j = 0; j < TN; j++) b[j] = Bs[kk][tx*TN + j];
#pragma unroll
            for (int i = 0; i < TM; i++)
#pragma unroll
                for (int j = 0; j < TN; j++)
                    acc[i][j] = fmaf(a[i], b[j], acc[i][j]);
        }
        __syncthreads();
    }

#pragma unroll
    for (int i = 0; i < TM; i++) {
        int row = bm + ty*TM + i;
#pragma unroll
        for (int j = 0; j < TN; j += 2) {
            int col = bn + tx*TN + j;
            *reinterpret_cast<__half2*>(C + (size_t)row*ldc + col) =
                __floats2half2_rn(acc[i][j] + bias[col], acc[i][j+1] + bias[col+1]);
        }
    }
}

// ---------------- RMSNorm (fp16 in), fp16 output ----------------
__global__ void rmsnorm_kernel(const __half* __restrict__ x, const float* __restrict__ w,
                               __half* __restrict__ oa) {
    int row = blockIdx.x;
    int tid = threadIdx.x;
    float4 v = ld_half4(x + (size_t)row*DM + tid*4);
    float ss = v.x*v.x + v.y*v.y + v.z*v.z + v.w*v.w;
#pragma unroll
    for (int o = 16; o; o >>= 1) ss += __shfl_xor_sync(0xffffffffu, ss, o);
    __shared__ float sred[4];
    if ((tid & 31) == 0) sred[tid >> 5] = ss;
    __syncthreads();
    float tot = sred[0] + sred[1] + sred[2] + sred[3];
    float scale = rsqrtf(tot * (1.f/(float)DM) + 1e-5f);
    float4 wv = reinterpret_cast<const float4*>(w)[tid];
    float o0 = v.x*scale*wv.x, o1 = v.y*scale*wv.y, o2 = v.z*scale*wv.z, o3 = v.w*scale*wv.w;
    size_t off = (size_t)row*DM + tid*4;
    __half2* oa2 = reinterpret_cast<__half2*>(oa + off);
    oa2[0] = __floats2half2_rn(o0, o1);
    oa2[1] = __floats2half2_rn(o2, o3);
}

// ---------------- depthwise causal conv(4) + bias + silu ----------------
__global__ void conv_silu_kernel(const __half* __restrict__ xz, const float* __restrict__ cw,
                                 const float* __restrict__ cb, __half* __restrict__ out) {
    size_t idx = (size_t)blockIdx.x * 256 + threadIdx.x;
    int e4 = (idx & (ED/4 - 1)) * 4;
    size_t rg = idx >> 8;
    int l0 = (int)(rg & (L_/4 - 1)) * 4;
    size_t row0 = (rg >> 8) * (size_t)L_ + l0;

    float4 b4 = *reinterpret_cast<const float4*>(&cb[e4]);
    float4 w0 = *reinterpret_cast<const float4*>(&cw[(size_t)(e4+0)*4]);
    float4 w1 = *reinterpret_cast<const float4*>(&cw[(size_t)(e4+1)*4]);
    float4 w2 = *reinterpret_cast<const float4*>(&cw[(size_t)(e4+2)*4]);
    float4 w3 = *reinterpret_cast<const float4*>(&cw[(size_t)(e4+3)*4]);

    float4 v[7];
#pragma unroll
    for (int i = 0; i < 7; i++) {
        int l = l0 - 3 + i;
        if (l >= 0) v[i] = ld_half4(xz + (row0 + (i - 3)) * (size_t)(2*ED) + e4);
        else        v[i] = make_float4(0.f, 0.f, 0.f, 0.f);
    }

#pragma unroll
    for (int j = 0; j < 4; j++) {
        float4 acc = b4;
        acc.x = fmaf(w0.x, v[j].x,   acc.x); acc.y = fmaf(w1.x, v[j].y,   acc.y);
        acc.z = fmaf(w2.x, v[j].z,   acc.z); acc.w = fmaf(w3.x, v[j].w,   acc.w);
        acc.x = fmaf(w0.y, v[j+1].x, acc.x); acc.y = fmaf(w1.y, v[j+1].y, acc.y);
        acc.z = fmaf(w2.y, v[j+1].z, acc.z); acc.w = fmaf(w3.y, v[j+1].w, acc.w);
        acc.x = fmaf(w0.z, v[j+2].x, acc.x); acc.y = fmaf(w1.z, v[j+2].y, acc.y);
        acc.z = fmaf(w2.z, v[j+2].z, acc.z); acc.w = fmaf(w3.z, v[j+2].w, acc.w);
        acc.x = fmaf(w0.w, v[j+3].x, acc.x); acc.y = fmaf(w1.w, v[j+3].y, acc.y);
        acc.z = fmaf(w2.w, v[j+3].z, acc.z); acc.w = fmaf(w3.w, v[j+3].w, acc.w);
        float4 o;
        o.x = acc.x * sigmoidf_(acc.x); o.y = acc.y * sigmoidf_(acc.y);
        o.z = acc.z * sigmoidf_(acc.z); o.w = acc.w * sigmoidf_(acc.w);
        uint2 st;
        *reinterpret_cast<__half2*>(&st.x) = __floats2half2_rn(o.x, o.y);
        *reinterpret_cast<__half2*>(&st.y) = __floats2half2_rn(o.z, o.w);
        *reinterpret_cast<uint2*>(&out[(row0 + j) * (size_t)ED + e4]) = st;
    }
}

// ---------------- scan pass A (256 threads, CH=8) ----------------
__global__ __launch_bounds__(256)
void scan_passA(const __half* __restrict__ delta, const __half* __restrict__ u,
                const __half* __restrict__ dbc, const float* __restrict__ A_log,
                float* __restrict__ hloc, float* __restrict__ Pout) {
    __shared__ float sB[LC][NST];
    int e = blockIdx.x * 256 + threadIdx.x;
    int c = blockIdx.y, b = blockIdx.z;
    for (int i = threadIdx.x; i < LC*NST; i += 256) {
        int row = i >> 4, col = i & 15;
        sB[row][col] = __half2float(dbc[(size_t)(b*L_ + c*LC + row)*64 + 32 + col]);
    }
    __syncthreads();

    float A[NST];
    bool fast = true;
#pragma unroll
    for (int n = 0; n < NST; n++) {
        float a = -__expf(A_log[(size_t)e*NST + n]);
        A[n] = a;
        fast = fast && (fabsf(a + (float)(n+1)) < 1e-4f * (float)(n+1));
    }

    float h[NST];
#pragma unroll
    for (int n = 0; n < NST; n++) h[n] = 0.f;
    float sd = 0.f;
    const __half* dp = delta + (size_t)(b*L_ + c*LC)*ED + e;
    const __half* up = u     + (size_t)(b*L_ + c*LC)*ED + e;

    if (fast) {
        for (int l = 0; l < LC; l++) {
            float dl = __half2float(dp[(size_t)l*ED]);
            float ul = __half2float(up[(size_t)l*ED]);
            float r  = __expf(-dl);
            float du = dl * ul;
            sd += dl;
            float pw[16];
            powers16(r, pw);
#pragma unroll
            for (int n = 0; n < NST; n++)
                h[n] = fmaf(pw[n], h[n], du * sB[l][n]);
        }
    } else {
        for (int l = 0; l < LC; l++) {
            float dl = __half2float(dp[(size_t)l*ED]);
            float ul = __half2float(up[(size_t)l*ED]);
            float du = dl * ul;
            sd += dl;
#pragma unroll
            for (int n = 0; n < NST; n++) {
                float dA = __expf(dl * A[n]);
                h[n] = fmaf(dA, h[n], du * sB[l][n]);
            }
        }
    }
    size_t o = ((size_t)(b*CH + c)*ED + e)*NST;
#pragma unroll
    for (int n4 = 0; n4 < NST; n4 += 4)
        *reinterpret_cast<float4*>(&hloc[o + n4]) =
            make_float4(h[n4], h[n4+1], h[n4+2], h[n4+3]);
#pragma unroll
    for (int n4 = 0; n4 < NST; n4 += 4)
        *reinterpret_cast<float4*>(&Pout[o + n4]) =
            make_float4(__expf(A[n4]*sd), __expf(A[n4+1]*sd),
                        __expf(A[n4+2]*sd), __expf(A[n4+3]*sd));
}

// ---------------- scan combine ----------------
__global__ void scan_combine(const float* __restrict__ hloc, const float* __restrict__ P,
                             float* __restrict__ Hin) {
    int idx = blockIdx.x * 256 + threadIdx.x;
    int n = idx & 15;
    int e = (idx >> 4) & (ED-1);
    int b = idx >> 14;
    float H = 0.f;
#pragma unroll
    for (int c = 0; c < CH; c++) {
        size_t o = ((size_t)(b*CH + c)*ED + e)*NST + n;
        Hin[o] = H;
        H = fmaf(P[o], H, hloc[o]);
    }
}

// ---------------- scan pass B (256 threads, CH=8) ----------------
__global__ __launch_bounds__(256)
void scan_passB(const __half* __restrict__ delta, const __half* __restrict__ u,
                const __half* __restrict__ dbc, const __half* __restrict__ xz,
                const float* __restrict__ A_log, const float* __restrict__ Dv,
                const float* __restrict__ Hin, __half* __restrict__ ya) {
    __shared__ float sB[LC][NST];
    __shared__ float sC[LC][NST];
    int e = blockIdx.x * 256 + threadIdx.x;
    int c = blockIdx.y, b = blockIdx.z;
    for (int i = threadIdx.x; i < LC*32; i += 256) {
        int row = i >> 5, col = i & 31;
        float v = __half2float(dbc[(size_t)(b*L_ + c*LC + row)*64 + 32 + col]);
        if (col < 16) sB[row][col] = v; else sC[row][col-16] = v;
    }
    __syncthreads();

    float A[NST];
    bool fast = true;
#pragma unroll
    for (int n = 0; n < NST; n++) {
        float a = -__expf(A_log[(size_t)e*NST + n]);
        A[n] = a;
        fast = fast && (fabsf(a + (float)(n+1)) < 1e-4f * (float)(n+1));
    }

    float h[NST];
    size_t oH = ((size_t)(b*CH + c)*ED + e)*NST;
#pragma unroll
    for (int n4 = 0; n4 < NST; n4 += 4) {
        float4 v = *reinterpret_cast<const float4*>(&Hin[oH + n4]);
        h[n4+0] = v.x; h[n4+1] = v.y; h[n4+2] = v.z; h[n4+3] = v.w;
    }
    float Dp = Dv[e];

    const __half* dp = delta + (size_t)(b*L_ + c*LC)*ED + e;
    const __half* up = u     + (size_t)(b*L_ + c*LC)*ED + e;
    const __half* zp = xz    + (size_t)(b*L_ + c*LC)*(2*ED) + ED + e;
    size_t yo = (size_t)(b*L_ + c*LC)*ED + e;

    if (fast) {
        for (int l = 0; l < LC; l++) {
            float dl = __half2float(dp[(size_t)l*ED]);
            float ul = __half2float(up[(size_t)l*ED]);
            float r  = __expf(-dl);
            float du = dl * ul;
            float y  = 0.f;
            float pw[16];
            powers16(r, pw);
#pragma unroll
            for (int n = 0; n < NST; n++) {
                h[n] = fmaf(pw[n], h[n], du * sB[l][n]);
                y = fmaf(h[n], sC[l][n], y);
            }
            float zl = __half2float(zp[(size_t)l*(2*ED)]);
            float yt = fmaf(Dp, ul, y) * zl * sigmoidf_(zl);
            ya[yo + (size_t)l*ED] = __float2half_rn(yt);
        }
    } else {
        for (int l = 0; l < LC; l++) {
            float dl = __half2float(dp[(size_t)l*ED]);
            float ul = __half2float(up[(size_t)l*ED]);
            float du = dl * ul;
            float y  = 0.f;
#pragma unroll
            for (int n = 0; n < NST; n++) {
                float dA = __expf(dl * A[n]);
                h[n] = fmaf(dA, h[n], du * sB[l][n]);
                y = fmaf(h[n], sC[l][n], y);
            }
            float zl = __half2float(zp[(size_t)l*(2*ED)]);
            float yt = fmaf(Dp, ul, y) * zl * sigmoidf_(zl);
            ya[yo + (size_t)l*ED] = __float2half_rn(yt);
        }
    }
}

// ---------------- head (fp16 h) ----------------
__global__ void head_kernel(const __half* __restrict__ h, const float* __restrict__ hw,
                            const float* __restrict__ hb, float* __restrict__ out) {
    int w    = blockIdx.x * 8 + (threadIdx.x >> 5);
    int lane = threadIdx.x & 31;
    int n = w % 3072;
    int b = w / 3072;
    const __half* hr = h + ((size_t)b*L_ + (L_-1))*DM;
    const float4* wr4 = reinterpret_cast<const float4*>(hw + (size_t)n*DM);
    float s = 0.f;
#pragma unroll
    for (int i = 0; i < 4; i++) {
        int k4 = lane + i*32;
        float4 a = ld_half4(hr + 4*k4);
        float4 ww = wr4[k4];
        s += a.x*ww.x + a.y*ww.y + a.z*ww.z + a.w*ww.w;
    }
#pragma unroll
    for (int o = 16; o; o >>= 1) s += __shfl_xor_sync(0xffffffffu, s, o);
    if (lane == 0) {
        int c = n & 31, t = n >> 5;
        out[(size_t)b*3072 + (size_t)c*96 + t] = s + hb[n];
    }
}

// ---------------- launch ----------------
extern "C" void kernel_launch(void* const* d_in, const int* in_sizes, int n_in,
                              void* d_out, int out_size) {
    const float* x        = (const float*)d_in[0];
    const float* embed_w  = (const float*)d_in[1];
    const float* embed_b  = (const float*)d_in[2];
    const float* norm_w   = (const float*)d_in[3];
    const float* in_w     = (const float*)d_in[4];
    const float* conv_w   = (const float*)d_in[5];
    const float* conv_b   = (const float*)d_in[6];
    const float* xp_w     = (const float*)d_in[7];
    const float* dt_w     = (const float*)d_in[8];
    const float* dt_b     = (const float*)d_in[9];
    const float* A_log    = (const float*)d_in[10];
    const float* Dv       = (const float*)d_in[11];
    const float* out_w    = (const float*)d_in[12];
    const float* head_w   = (const float*)d_in[13];
    const float* head_b   = (const float*)d_in[14];
    float* out = (float*)d_out;

    float *hloc, *P, *Hin, *xT;
    __half *h, *xz, *xc, *dbc, *delta, *a, *wi, *wo, *wx, *wd;
    cudaGetSymbolAddress((void**)&h,     g_h);
    cudaGetSymbolAddress((void**)&xz,    g_xz);
    cudaGetSymbolAddress((void**)&xc,    g_xc);
    cudaGetSymbolAddress((void**)&dbc,   g_dbc);
    cudaGetSymbolAddress((void**)&delta, g_delta);
    cudaGetSymbolAddress((void**)&hloc,  g_hloc);
    cudaGetSymbolAddress((void**)&P,     g_P);
    cudaGetSymbolAddress((void**)&Hin,   g_Hin);
    cudaGetSymbolAddress((void**)&xT,    g_xT);
    cudaGetSymbolAddress((void**)&a,     g_a);
    cudaGetSymbolAddress((void**)&wi,    g_wi);
    cudaGetSymbolAddress((void**)&wo,    g_wo);
    cudaGetSymbolAddress((void**)&wx,    g_wx);
    cudaGetSymbolAddress((void**)&wd,    g_wd);

    cudaFuncSetAttribute(mma_gemm<0>, cudaFuncAttributeMaxDynamicSharedMemorySize, MMA_SMEM);
    cudaFuncSetAttribute(mma_gemm<1>, cudaFuncAttributeMaxDynamicSharedMemorySize, MMA_SMEM);
    cudaFuncSetAttribute(mma_gemm<2>, cudaFuncAttributeMaxDynamicSharedMemorySize, MMA_SMEM);
    cudaFuncSetAttribute(tc_gemm_n64, cudaFuncAttributeMaxDynamicSharedMemorySize, N64_SMEM);

    transpose_x_kernel<<<dim3(L_/32, B_), dim3(32, 32)>>>(x, xT);
    cvt_fp16_kernel<<<(NL*2*ED*DM + 255)/256, 256>>>(in_w,  wi, NL*2*ED*DM);
    cvt_fp16_kernel<<<(NL*DM*ED   + 255)/256, 256>>>(out_w, wo, NL*DM*ED);
    cvt_fp16_kernel<<<(NL*64*ED   + 255)/256, 256>>>(xp_w,  wx, NL*64*ED);
    cvt_fp16_kernel<<<(NL*ED*DR   + 255)/256, 256>>>(dt_w,  wd, NL*ED*DR);
    sgemm_kernel<128,128,16,8,8><<<dim3(DM/128, MROWS/128), 256>>>(
        xT, embed_w, h, embed_b, MROWS, DM, 32, 32, 32, DM);

    for (int i = 0; i < NL; i++) {
        rmsnorm_kernel<<<MROWS, 128>>>(h, norm_w + (size_t)i*DM, a);

        // xz = rms @ in_proj^T
        mma_gemm<0><<<dim3(2*ED/256, MROWS/128), 512, MMA_SMEM>>>(
            a, wi + (size_t)i*2*ED*DM, xz, nullptr, DM, DM, DM, 2*ED);

        // depthwise causal conv + silu
        conv_silu_kernel<<<(MROWS/4)*(ED/4)/256, 256>>>(
            xz, conv_w + (size_t)i*ED*4, conv_b + (size_t)i*ED, xc);

        // dbc = xc @ x_proj^T
        tc_gemm_n64<<<dim3(1, MROWS/128), 256, N64_SMEM>>>(
            xc, wx + (size_t)i*64*ED, dbc, ED, ED, ED, 64);

        // delta = softplus(dbc[:, :32] @ dt_w^T + dt_b)
        mma_gemm<2><<<dim3(ED/256, MROWS/128), 512, MMA_SMEM>>>(
            dbc, wd + (size_t)i*ED*DR, delta, dt_b + (size_t)i*ED, DR, 64, DR, ED);

        // chunked selective scan
        scan_passA<<<dim3(ED/256, CH, B_), 256>>>(
            delta, xc, dbc, A_log + (size_t)i*ED*NST, hloc, P);
        scan_combine<<<(B_*ED*NST)/256, 256>>>(hloc, P, Hin);
        scan_passB<<<dim3(ED/256, CH, B_), 256>>>(
            delta, xc, dbc, xz, A_log + (size_t)i*ED*NST, Dv + (size_t)i*ED, Hin, a);

        // h += y @ out_proj^T  (fp16 residual RMW)
        mma_gemm<1><<<dim3(DM/256, MROWS/128), 512, MMA_SMEM>>>(
            a, wo + (size_t)i*DM*ED, h, nullptr, ED, ED, ED, DM);
    }

    head_kernel<<<(B_*3072)/8, 256>>>(h, head_w, head_b, out);
}